// round 1
// baseline (speedup 1.0000x reference)
#include <cuda_runtime.h>
#include <math.h>

#define BSZ 4096
#define DIM 256
#define NN ((size_t)BSZ * (size_t)BSZ)

// Scratch: three 4096x4096 distance matrices (192 MB), norms, accumulators.
__device__ float  g_dist[3u * 16777216u];
__device__ float  g_norm[2][BSZ];
__device__ double g_distsum[3];
__device__ double g_expsum[3];

// ---------------------------------------------------------------------------
__global__ void zero_kernel() {
    int i = threadIdx.x;
    if (i < 3) { g_distsum[i] = 0.0; g_expsum[i] = 0.0; }
}

// ---------------------------------------------------------------------------
// Row squared-norms: one warp per row (8192 rows total).
__global__ void norms_kernel(const float* __restrict__ xs,
                             const float* __restrict__ xt) {
    int warp = threadIdx.x >> 5;
    int lane = threadIdx.x & 31;
    int row  = blockIdx.x * 8 + warp;        // 0..8191
    int which = (row >= BSZ) ? 1 : 0;
    int r = row - which * BSZ;
    const float* src = which ? xt : xs;
    const float4* p = (const float4*)(src + (size_t)r * DIM);
    float s = 0.f;
    #pragma unroll
    for (int i = lane; i < DIM / 4; i += 32) {
        float4 v = p[i];
        s += v.x * v.x + v.y * v.y + v.z * v.z + v.w * v.w;
    }
    #pragma unroll
    for (int o = 16; o > 0; o >>= 1) s += __shfl_xor_sync(0xffffffffu, s, o);
    if (lane == 0) g_norm[which][r] = s;
}

// ---------------------------------------------------------------------------
// 128x128x16 register-blocked SGEMM -> distance epilogue.
// blockIdx.z selects the pair: 0 = (xs,xs), 1 = (xt,xt), 2 = (xs,xt).
__global__ void __launch_bounds__(256, 2)
dist_kernel(const float* __restrict__ xs, const float* __restrict__ xt) {
    __shared__ float As[16][128];
    __shared__ float Bs[16][128];
    __shared__ double red[256];

    const int z = blockIdx.z;
    const float* Am = (z == 1) ? xt : xs;
    const float* Bm = (z == 0) ? xs : xt;
    const float* nA = g_norm[(z == 1) ? 1 : 0];
    const float* nB = g_norm[(z == 0) ? 0 : 1];

    const int rowBase = blockIdx.y * 128;
    const int colBase = blockIdx.x * 128;
    const int tid = threadIdx.x;
    const int tx = tid & 15;       // column group
    const int ty = tid >> 4;       // row group

    float acc[8][8];
    #pragma unroll
    for (int i = 0; i < 8; i++)
        #pragma unroll
        for (int j = 0; j < 8; j++) acc[i][j] = 0.f;

    for (int k0 = 0; k0 < DIM; k0 += 16) {
        // Load 128x16 tiles of A and B (transposed into smem as [k][row]).
        #pragma unroll
        for (int i = 0; i < 2; i++) {
            int s  = tid * 2 + i;      // 0..511 float4 slots
            int r  = s >> 2;           // row within tile
            int kq = s & 3;            // which float4 along k
            float4 va = *(const float4*)(Am + (size_t)(rowBase + r) * DIM + k0 + kq * 4);
            As[kq * 4 + 0][r] = va.x;
            As[kq * 4 + 1][r] = va.y;
            As[kq * 4 + 2][r] = va.z;
            As[kq * 4 + 3][r] = va.w;
            float4 vb = *(const float4*)(Bm + (size_t)(colBase + r) * DIM + k0 + kq * 4);
            Bs[kq * 4 + 0][r] = vb.x;
            Bs[kq * 4 + 1][r] = vb.y;
            Bs[kq * 4 + 2][r] = vb.z;
            Bs[kq * 4 + 3][r] = vb.w;
        }
        __syncthreads();

        #pragma unroll
        for (int kk = 0; kk < 16; kk++) {
            float a[8], b[8];
            *(float4*)(a)     = *(const float4*)&As[kk][ty * 8];
            *(float4*)(a + 4) = *(const float4*)&As[kk][ty * 8 + 4];
            *(float4*)(b)     = *(const float4*)&Bs[kk][tx * 8];
            *(float4*)(b + 4) = *(const float4*)&Bs[kk][tx * 8 + 4];
            #pragma unroll
            for (int i = 0; i < 8; i++)
                #pragma unroll
                for (int j = 0; j < 8; j++)
                    acc[i][j] = fmaf(a[i], b[j], acc[i][j]);
        }
        __syncthreads();
    }

    // Epilogue: d = sqrt(max(|x|^2 + |y|^2 - 2 x.y, 0)); store + sum for mean.
    float na[8], nb[8];
    #pragma unroll
    for (int i = 0; i < 8; i++) na[i] = nA[rowBase + ty * 8 + i];
    #pragma unroll
    for (int j = 0; j < 8; j++) nb[j] = nB[colBase + tx * 8 + j];

    float* out = g_dist + (size_t)z * NN;
    float lsum = 0.f;
    #pragma unroll
    for (int i = 0; i < 8; i++) {
        float t[8];
        #pragma unroll
        for (int j = 0; j < 8; j++) {
            float sq = na[i] + nb[j] - 2.f * acc[i][j];
            sq = fmaxf(sq, 0.f);
            float d = sqrtf(sq);
            t[j] = d;
            lsum += d;
        }
        size_t off = (size_t)(rowBase + ty * 8 + i) * BSZ + colBase + tx * 8;
        *(float4*)(out + off)     = make_float4(t[0], t[1], t[2], t[3]);
        *(float4*)(out + off + 4) = make_float4(t[4], t[5], t[6], t[7]);
    }

    // Block reduce (double) and atomic into the per-matrix distance sum.
    red[tid] = (double)lsum;
    __syncthreads();
    #pragma unroll
    for (int s = 128; s > 0; s >>= 1) {
        if (tid < s) red[tid] += red[tid + s];
        __syncthreads();
    }
    if (tid == 0) atomicAdd(&g_distsum[z], red[0]);
}

// ---------------------------------------------------------------------------
// Exponent pass. alphas are powers of two: with e = exp(-d/(4m)) (alpha=2),
// the five kernels are e, e^2, e^4, e^8, e^16  -> ONE ex2 per element.
__global__ void exp_kernel() {
    __shared__ double red[256];
    const int z = blockIdx.y;
    double m = g_distsum[z] * (1.0 / ((double)BSZ * (double)BSZ));
    // exp(-d/(4m)) = ex2(d * (-log2(e)/(4m)))
    float c = (float)(-1.4426950408889634 / (4.0 * m));

    const float4* src = (const float4*)(g_dist + (size_t)z * NN);
    const size_t n4 = NN / 4;
    const size_t stride = (size_t)gridDim.x * blockDim.x;
    float lsum = 0.f;
    for (size_t i = (size_t)blockIdx.x * blockDim.x + threadIdx.x; i < n4; i += stride) {
        float4 v = src[i];
        float d[4] = {v.x, v.y, v.z, v.w};
        #pragma unroll
        for (int u = 0; u < 4; u++) {
            float t = d[u] * c;
            float e;
            asm("ex2.approx.ftz.f32 %0, %1;" : "=f"(e) : "f"(t));
            float e2 = e * e, e4 = e2 * e2, e8 = e4 * e4, e16 = e8 * e8;
            lsum += (e + e2) + (e4 + e8) + e16;
        }
    }

    red[threadIdx.x] = (double)lsum;
    __syncthreads();
    #pragma unroll
    for (int s = 128; s > 0; s >>= 1) {
        if (threadIdx.x < s) red[threadIdx.x] += red[threadIdx.x + s];
        __syncthreads();
    }
    if (threadIdx.x == 0) atomicAdd(&g_expsum[z], red[0]);
}

// ---------------------------------------------------------------------------
__global__ void final_kernel(float* out) {
    double total = g_expsum[0] + g_expsum[1] - 2.0 * g_expsum[2];
    double v = total / ((double)BSZ * ((double)BSZ - 1.0));
    float loss = sqrtf((float)v);   // negative -> nan
    out[0] = isnan(loss) ? 0.f : loss;
}

// ---------------------------------------------------------------------------
extern "C" void kernel_launch(void* const* d_in, const int* in_sizes, int n_in,
                              void* d_out, int out_size) {
    const float* xs = (const float*)d_in[0];
    const float* xt = (const float*)d_in[1];
    float* out = (float*)d_out;

    zero_kernel<<<1, 32>>>();
    norms_kernel<<<1024, 256>>>(xs, xt);
    dist_kernel<<<dim3(32, 32, 3), 256>>>(xs, xt);
    exp_kernel<<<dim3(1024, 3), 256>>>();
    final_kernel<<<1, 1>>>(out);
}

// round 4
// speedup vs baseline: 2.8278x; 2.8278x over previous
#include <cuda_runtime.h>
#include <cuda_fp16.h>
#include <math.h>
#include <stdint.h>

#define BSZ 4096
#define DIM 256
#define NN ((size_t)BSZ * (size_t)BSZ)

// Scratch: three 4096x4096 fp16 distance matrices (96 MB), norms, accumulators.
__device__ __align__(16) __half g_dist[3u * 16777216u];
__device__ float  g_norm[2][BSZ];
__device__ double g_distsum[3];
__device__ double g_expsum[3];

// ---------------------------------------------------------------------------
__global__ void zero_kernel() {
    int i = threadIdx.x;
    if (i < 3) { g_distsum[i] = 0.0; g_expsum[i] = 0.0; }
}

// ---------------------------------------------------------------------------
// Row squared-norms: one warp per row (8192 rows).
__global__ void norms_kernel(const float* __restrict__ xs,
                             const float* __restrict__ xt) {
    int warp = threadIdx.x >> 5;
    int lane = threadIdx.x & 31;
    int row  = blockIdx.x * 8 + warp;        // 0..8191
    int which = (row >= BSZ) ? 1 : 0;
    int r = row - which * BSZ;
    const float* src = which ? xt : xs;
    const float4* p = (const float4*)(src + (size_t)r * DIM);
    float s = 0.f;
    #pragma unroll
    for (int i = lane; i < DIM / 4; i += 32) {
        float4 v = p[i];
        s += v.x * v.x + v.y * v.y + v.z * v.z + v.w * v.w;
    }
    #pragma unroll
    for (int o = 16; o > 0; o >>= 1) s += __shfl_xor_sync(0xffffffffu, s, o);
    if (lane == 0) g_norm[which][r] = s;
}

// ---------------------------------------------------------------------------
// tf32 HMMA distance GEMM: 128x128 CTA tile, 8 warps (2x4), warp tile 64x32.
// K=256 in 8 chunks of 32, cp.async double-buffered. m16n8k8 tf32 mma.
// ---------------------------------------------------------------------------
#define CHUNK 32
#define SM_STRIDE 36                       // floats per row (conflict-free)
#define SM_TILE   (128 * SM_STRIDE)        // 4608 floats per tile buffer
#define SM_BYTES  (4 * SM_TILE * 4)        // A0,A1,B0,B1 = 73728 bytes

__device__ __forceinline__ uint32_t smem_u32(const void* p) {
    uint32_t a;
    asm("{ .reg .u64 t; cvta.to.shared.u64 t, %1; cvt.u32.u64 %0, t; }" : "=r"(a) : "l"(p));
    return a;
}
__device__ __forceinline__ uint32_t to_tf32(float f) {
    uint32_t u;
    asm("cvt.rna.tf32.f32 %0, %1;" : "=r"(u) : "f"(f));
    return u;
}
__device__ __forceinline__ void mma_tf32(float* c, const uint32_t* a, const uint32_t* b) {
    asm volatile(
        "mma.sync.aligned.m16n8k8.row.col.f32.tf32.tf32.f32 "
        "{%0,%1,%2,%3}, {%4,%5,%6,%7}, {%8,%9}, {%0,%1,%2,%3};"
        : "+f"(c[0]), "+f"(c[1]), "+f"(c[2]), "+f"(c[3])
        : "r"(a[0]), "r"(a[1]), "r"(a[2]), "r"(a[3]), "r"(b[0]), "r"(b[1]));
}

__global__ void __launch_bounds__(256, 2)
dist_tc_kernel(const float* __restrict__ xs, const float* __restrict__ xt) {
    extern __shared__ float sm[];
    __shared__ double red[256];

    const int z = blockIdx.z;
    const float* Am = (z == 1) ? xt : xs;
    const float* Bm = (z == 0) ? xs : xt;
    const int za = (z == 1) ? 1 : 0;
    const int zb = (z == 0) ? 0 : 1;
    const int rowBase = blockIdx.y * 128;
    const int colBase = blockIdx.x * 128;

    const int tid = threadIdx.x;
    const int wid = tid >> 5;
    const int lid = tid & 31;
    const int wm = wid >> 2;       // 0..1
    const int wn = wid & 3;        // 0..3
    const int l4 = lid >> 2;       // 0..7
    const int lk = lid & 3;        // 0..3
    const int mrow0 = wm * 64;
    const int ncol0 = wn * 32;

    float acc[4][4][4];
    #pragma unroll
    for (int i = 0; i < 4; i++)
        #pragma unroll
        for (int j = 0; j < 4; j++)
            #pragma unroll
            for (int u = 0; u < 4; u++) acc[i][j][u] = 0.f;

    const uint32_t smb = smem_u32(sm);

    // cp.async loader for one chunk into buffer buf.
    auto load_chunk = [&](int c, int buf) {
        const int k0 = c * CHUNK;
        #pragma unroll
        for (int it = 0; it < 8; it++) {
            int idx = it * 256 + tid;          // 0..2047 float4 slots
            int mat = idx >> 10;               // 0=A, 1=B
            int rem = idx & 1023;
            int row = rem >> 3;                // 0..127
            int g   = rem & 7;                 // float4 within 32-float row
            const float* gp = (mat ? Bm : Am) +
                (size_t)((mat ? colBase : rowBase) + row) * DIM + k0 + g * 4;
            uint32_t sa = smb + ((mat * 2 + buf) * SM_TILE + row * SM_STRIDE + g * 4) * 4;
            asm volatile("cp.async.cg.shared.global [%0], [%1], 16;"
                         :: "r"(sa), "l"(gp));
        }
        asm volatile("cp.async.commit_group;");
    };

    load_chunk(0, 0);

    for (int c = 0; c < 8; c++) {
        const int buf = c & 1;
        if (c < 7) {
            load_chunk(c + 1, buf ^ 1);
            asm volatile("cp.async.wait_group 1;");
        } else {
            asm volatile("cp.async.wait_group 0;");
        }
        __syncthreads();

        const float* A = sm + buf * SM_TILE;
        const float* B = sm + (2 + buf) * SM_TILE;

        #pragma unroll
        for (int ks = 0; ks < 4; ks++) {
            const int kb = ks * 8;
            uint32_t a[4][4], b[4][2];
            #pragma unroll
            for (int mt = 0; mt < 4; mt++) {
                int r = mrow0 + mt * 16 + l4;
                a[mt][0] = to_tf32(A[r * SM_STRIDE + kb + lk]);
                a[mt][1] = to_tf32(A[(r + 8) * SM_STRIDE + kb + lk]);
                a[mt][2] = to_tf32(A[r * SM_STRIDE + kb + lk + 4]);
                a[mt][3] = to_tf32(A[(r + 8) * SM_STRIDE + kb + lk + 4]);
            }
            #pragma unroll
            for (int nt = 0; nt < 4; nt++) {
                int cc = ncol0 + nt * 8 + l4;
                b[nt][0] = to_tf32(B[cc * SM_STRIDE + kb + lk]);
                b[nt][1] = to_tf32(B[cc * SM_STRIDE + kb + lk + 4]);
            }
            #pragma unroll
            for (int mt = 0; mt < 4; mt++)
                #pragma unroll
                for (int nt = 0; nt < 4; nt++)
                    mma_tf32(acc[mt][nt], a[mt], b[nt]);
        }
        __syncthreads();
    }

    // Epilogue: d = sqrt(max(na + nb - 2*dot, 0)), store fp16, sum for mean.
    // For the self-distance matrices (z<2), the exact diagonal is forced to 0:
    // tf32 noise through sqrt's singularity at 0 otherwise biases kxx/kyy.
    float na0[4], na1[4], nb0[4], nb1[4];
    #pragma unroll
    for (int mt = 0; mt < 4; mt++) {
        int r = rowBase + mrow0 + mt * 16 + l4;
        na0[mt] = g_norm[za][r];
        na1[mt] = g_norm[za][r + 8];
    }
    #pragma unroll
    for (int nt = 0; nt < 4; nt++) {
        int cc = colBase + ncol0 + nt * 8 + 2 * lk;
        nb0[nt] = g_norm[zb][cc];
        nb1[nt] = g_norm[zb][cc + 1];
    }

    const bool self = (z < 2);
    __half* gd = g_dist + (size_t)z * NN;
    float lsum = 0.f;
    #pragma unroll
    for (int mt = 0; mt < 4; mt++) {
        int row0 = rowBase + mrow0 + mt * 16 + l4;
        #pragma unroll
        for (int nt = 0; nt < 4; nt++) {
            int col = colBase + ncol0 + nt * 8 + 2 * lk;
            float* ac = acc[mt][nt];
            float d00 = sqrtf(fmaxf(na0[mt] + nb0[nt] - 2.f * ac[0], 0.f));
            float d01 = sqrtf(fmaxf(na0[mt] + nb1[nt] - 2.f * ac[1], 0.f));
            float d10 = sqrtf(fmaxf(na1[mt] + nb0[nt] - 2.f * ac[2], 0.f));
            float d11 = sqrtf(fmaxf(na1[mt] + nb1[nt] - 2.f * ac[3], 0.f));
            if (self) {
                if (row0 == col)         d00 = 0.f;
                if (row0 == col + 1)     d01 = 0.f;
                if (row0 + 8 == col)     d10 = 0.f;
                if (row0 + 8 == col + 1) d11 = 0.f;
            }
            lsum += (d00 + d01) + (d10 + d11);
            *(__half2*)(gd + (size_t)row0 * BSZ + col) = __floats2half2_rn(d00, d01);
            *(__half2*)(gd + (size_t)(row0 + 8) * BSZ + col) = __floats2half2_rn(d10, d11);
        }
    }

    red[tid] = (double)lsum;
    __syncthreads();
    #pragma unroll
    for (int s = 128; s > 0; s >>= 1) {
        if (tid < s) red[tid] += red[tid + s];
        __syncthreads();
    }
    if (tid == 0) atomicAdd(&g_distsum[z], red[0]);
}

// ---------------------------------------------------------------------------
// Exponent pass. alphas are powers of two: with e = exp(-d/(4m)) (alpha=2),
// the five kernels are e, e^2, e^4, e^8, e^16  -> ONE ex2 per element.
__global__ void exp_kernel() {
    __shared__ double red[256];
    const int z = blockIdx.y;
    double m = g_distsum[z] * (1.0 / ((double)BSZ * (double)BSZ));
    float c = (float)(-1.4426950408889634 / (4.0 * m));

    const uint4* src = (const uint4*)(g_dist + (size_t)z * NN);
    const size_t n8 = NN / 8;
    const size_t stride = (size_t)gridDim.x * blockDim.x;
    float lsum = 0.f;
    for (size_t i = (size_t)blockIdx.x * blockDim.x + threadIdx.x; i < n8; i += stride) {
        uint4 v = src[i];
        uint32_t w[4] = {v.x, v.y, v.z, v.w};
        #pragma unroll
        for (int u = 0; u < 4; u++) {
            float2 f = __half22float2(*(__half2*)&w[u]);
            float d2[2] = {f.x, f.y};
            #pragma unroll
            for (int q = 0; q < 2; q++) {
                float t = d2[q] * c;
                float e;
                asm("ex2.approx.ftz.f32 %0, %1;" : "=f"(e) : "f"(t));
                float e2 = e * e, e4 = e2 * e2, e8 = e4 * e4, e16 = e8 * e8;
                lsum += (e + e2) + (e4 + e8) + e16;
            }
        }
    }

    red[threadIdx.x] = (double)lsum;
    __syncthreads();
    #pragma unroll
    for (int s = 128; s > 0; s >>= 1) {
        if (threadIdx.x < s) red[threadIdx.x] += red[threadIdx.x + s];
        __syncthreads();
    }
    if (threadIdx.x == 0) atomicAdd(&g_expsum[z], red[0]);
}

// ---------------------------------------------------------------------------
__global__ void final_kernel(float* out) {
    double total = g_expsum[0] + g_expsum[1] - 2.0 * g_expsum[2];
    double v = total / ((double)BSZ * ((double)BSZ - 1.0));
    float loss = sqrtf((float)v);
    out[0] = isnan(loss) ? 0.f : loss;
}

// ---------------------------------------------------------------------------
extern "C" void kernel_launch(void* const* d_in, const int* in_sizes, int n_in,
                              void* d_out, int out_size) {
    const float* xs = (const float*)d_in[0];
    const float* xt = (const float*)d_in[1];
    float* out = (float*)d_out;

    static int configured = 0;
    if (!configured) {
        cudaFuncSetAttribute(dist_tc_kernel,
                             cudaFuncAttributeMaxDynamicSharedMemorySize, SM_BYTES);
        configured = 1;
    }

    zero_kernel<<<1, 32>>>();
    norms_kernel<<<1024, 256>>>(xs, xt);
    dist_tc_kernel<<<dim3(32, 32, 3), 256, SM_BYTES>>>(xs, xt);
    exp_kernel<<<dim3(1024, 3), 256>>>();
    final_kernel<<<1, 1>>>(out);
}

// round 6
// speedup vs baseline: 4.1480x; 1.4669x over previous
#include <cuda_runtime.h>
#include <cuda_fp16.h>
#include <math.h>
#include <stdint.h>

#define BSZ 4096
#define DIM 256

// Tile-compacted scratch: dxx/dyy only upper triangle (528 tiles each),
// dxy all 1024 tiles. 2080 tiles x 128x128 fp16 = 68 MB.
#define TILES_SELF 528
#define TILES_T1   1056
#define TILES_ALL  2080
#define TILE_ELEMS 16384

__device__ __align__(16) __half g_dist[(size_t)TILES_ALL * TILE_ELEMS];
__device__ float  g_norm[2][BSZ];
__device__ double g_distsum[3];
__device__ double g_expsum[3];

// ---------------------------------------------------------------------------
__global__ void zero_kernel() {
    int i = threadIdx.x;
    if (i < 3) { g_distsum[i] = 0.0; g_expsum[i] = 0.0; }
}

// ---------------------------------------------------------------------------
// Row squared-norms: one warp per row (8192 rows).
__global__ void norms_kernel(const float* __restrict__ xs,
                             const float* __restrict__ xt) {
    int warp = threadIdx.x >> 5;
    int lane = threadIdx.x & 31;
    int row  = blockIdx.x * 8 + warp;        // 0..8191
    int which = (row >= BSZ) ? 1 : 0;
    int r = row - which * BSZ;
    const float* src = which ? xt : xs;
    const float4* p = (const float4*)(src + (size_t)r * DIM);
    float s = 0.f;
    #pragma unroll
    for (int i = lane; i < DIM / 4; i += 32) {
        float4 v = p[i];
        s += v.x * v.x + v.y * v.y + v.z * v.z + v.w * v.w;
    }
    #pragma unroll
    for (int o = 16; o > 0; o >>= 1) s += __shfl_xor_sync(0xffffffffu, s, o);
    if (lane == 0) g_norm[which][r] = s;
}

// ---------------------------------------------------------------------------
// Tile decode: t -> (z, by, bx, weight). For z<2 only by<=bx tiles exist.
__device__ __forceinline__ void tri_decode(int i, int& by, int& bx) {
    int b = 0;
    while (i >= 32 - b) { i -= 32 - b; b++; }
    by = b; bx = b + i;
}
__device__ __forceinline__ void tile_decode(int t, int& z, int& by, int& bx,
                                            float& w) {
    if (t < TILES_SELF)      { z = 0; tri_decode(t, by, bx); }
    else if (t < TILES_T1)   { z = 1; tri_decode(t - TILES_SELF, by, bx); }
    else                     { z = 2; int l = t - TILES_T1; by = l >> 5; bx = l & 31; }
    w = (z < 2 && by != bx) ? 2.0f : 1.0f;
}

// ---------------------------------------------------------------------------
// tf32 HMMA distance GEMM: one 128x128 tile per CTA, 8 warps (2x4).
// K=256 in 8 chunks of 32, cp.async double-buffered, m16n8k8 tf32 mma.
// ---------------------------------------------------------------------------
#define CHUNK 32
#define SM_STRIDE 36
#define SM_TILE   (128 * SM_STRIDE)
#define SM_BYTES  (4 * SM_TILE * 4)        // 73728 bytes

__device__ __forceinline__ uint32_t smem_u32(const void* p) {
    uint32_t a;
    asm("{ .reg .u64 t; cvta.to.shared.u64 t, %1; cvt.u32.u64 %0, t; }" : "=r"(a) : "l"(p));
    return a;
}
__device__ __forceinline__ uint32_t to_tf32(float f) {
    uint32_t u;
    asm("cvt.rna.tf32.f32 %0, %1;" : "=r"(u) : "f"(f));
    return u;
}
__device__ __forceinline__ void mma_tf32(float* c, const uint32_t* a, const uint32_t* b) {
    asm volatile(
        "mma.sync.aligned.m16n8k8.row.col.f32.tf32.tf32.f32 "
        "{%0,%1,%2,%3}, {%4,%5,%6,%7}, {%8,%9}, {%0,%1,%2,%3};"
        : "+f"(c[0]), "+f"(c[1]), "+f"(c[2]), "+f"(c[3])
        : "r"(a[0]), "r"(a[1]), "r"(a[2]), "r"(a[3]), "r"(b[0]), "r"(b[1]));
}

__global__ void __launch_bounds__(256, 2)
dist_tc_kernel(const float* __restrict__ xs, const float* __restrict__ xt) {
    extern __shared__ float sm[];
    __shared__ double red[256];

    int z, by, bx; float w;
    tile_decode(blockIdx.x, z, by, bx, w);

    const float* Am = (z == 1) ? xt : xs;
    const float* Bm = (z == 0) ? xs : xt;
    const int za = (z == 1) ? 1 : 0;
    const int zb = (z == 0) ? 0 : 1;
    const int rowBase = by * 128;
    const int colBase = bx * 128;

    const int tid = threadIdx.x;
    const int wid = tid >> 5;
    const int lid = tid & 31;
    const int wm = wid >> 2;
    const int wn = wid & 3;
    const int l4 = lid >> 2;
    const int lk = lid & 3;
    const int mrow0 = wm * 64;
    const int ncol0 = wn * 32;

    float acc[4][4][4];
    #pragma unroll
    for (int i = 0; i < 4; i++)
        #pragma unroll
        for (int j = 0; j < 4; j++)
            #pragma unroll
            for (int u = 0; u < 4; u++) acc[i][j][u] = 0.f;

    const uint32_t smb = smem_u32(sm);

    auto load_chunk = [&](int c, int buf) {
        const int k0 = c * CHUNK;
        #pragma unroll
        for (int it = 0; it < 8; it++) {
            int idx = it * 256 + tid;
            int mat = idx >> 10;
            int rem = idx & 1023;
            int row = rem >> 3;
            int g   = rem & 7;
            const float* gp = (mat ? Bm : Am) +
                (size_t)((mat ? colBase : rowBase) + row) * DIM + k0 + g * 4;
            uint32_t sa = smb + ((mat * 2 + buf) * SM_TILE + row * SM_STRIDE + g * 4) * 4;
            asm volatile("cp.async.cg.shared.global [%0], [%1], 16;"
                         :: "r"(sa), "l"(gp));
        }
        asm volatile("cp.async.commit_group;");
    };

    load_chunk(0, 0);

    for (int c = 0; c < 8; c++) {
        const int buf = c & 1;
        if (c < 7) {
            load_chunk(c + 1, buf ^ 1);
            asm volatile("cp.async.wait_group 1;");
        } else {
            asm volatile("cp.async.wait_group 0;");
        }
        __syncthreads();

        const float* A = sm + buf * SM_TILE;
        const float* B = sm + (2 + buf) * SM_TILE;

        #pragma unroll
        for (int ks = 0; ks < 4; ks++) {
            const int kb = ks * 8;
            uint32_t a[4][4], b[4][2];
            #pragma unroll
            for (int mt = 0; mt < 4; mt++) {
                int r = mrow0 + mt * 16 + l4;
                a[mt][0] = to_tf32(A[r * SM_STRIDE + kb + lk]);
                a[mt][1] = to_tf32(A[(r + 8) * SM_STRIDE + kb + lk]);
                a[mt][2] = to_tf32(A[r * SM_STRIDE + kb + lk + 4]);
                a[mt][3] = to_tf32(A[(r + 8) * SM_STRIDE + kb + lk + 4]);
            }
            #pragma unroll
            for (int nt = 0; nt < 4; nt++) {
                int cc = ncol0 + nt * 8 + l4;
                b[nt][0] = to_tf32(B[cc * SM_STRIDE + kb + lk]);
                b[nt][1] = to_tf32(B[cc * SM_STRIDE + kb + lk + 4]);
            }
            #pragma unroll
            for (int mt = 0; mt < 4; mt++)
                #pragma unroll
                for (int nt = 0; nt < 4; nt++)
                    mma_tf32(acc[mt][nt], a[mt], b[nt]);
        }
        __syncthreads();
    }

    // Epilogue: d = sqrt(max(na + nb - 2*dot, 0)); exact self-diagonal -> 0.
    float na0[4], na1[4], nb0[4], nb1[4];
    #pragma unroll
    for (int mt = 0; mt < 4; mt++) {
        int r = rowBase + mrow0 + mt * 16 + l4;
        na0[mt] = g_norm[za][r];
        na1[mt] = g_norm[za][r + 8];
    }
    #pragma unroll
    for (int nt = 0; nt < 4; nt++) {
        int cc = colBase + ncol0 + nt * 8 + 2 * lk;
        nb0[nt] = g_norm[zb][cc];
        nb1[nt] = g_norm[zb][cc + 1];
    }

    const bool selfdiag = (z < 2) && (by == bx);
    __half* gd = g_dist + (size_t)blockIdx.x * TILE_ELEMS;
    float lsum = 0.f;
    #pragma unroll
    for (int mt = 0; mt < 4; mt++) {
        int lr0 = mrow0 + mt * 16 + l4;
        #pragma unroll
        for (int nt = 0; nt < 4; nt++) {
            int lc = ncol0 + nt * 8 + 2 * lk;
            float* ac = acc[mt][nt];
            float d00 = sqrtf(fmaxf(na0[mt] + nb0[nt] - 2.f * ac[0], 0.f));
            float d01 = sqrtf(fmaxf(na0[mt] + nb1[nt] - 2.f * ac[1], 0.f));
            float d10 = sqrtf(fmaxf(na1[mt] + nb0[nt] - 2.f * ac[2], 0.f));
            float d11 = sqrtf(fmaxf(na1[mt] + nb1[nt] - 2.f * ac[3], 0.f));
            if (selfdiag) {
                if (lr0 == lc)         d00 = 0.f;
                if (lr0 == lc + 1)     d01 = 0.f;
                if (lr0 + 8 == lc)     d10 = 0.f;
                if (lr0 + 8 == lc + 1) d11 = 0.f;
            }
            lsum += (d00 + d01) + (d10 + d11);
            *(__half2*)(gd + lr0 * 128 + lc)       = __floats2half2_rn(d00, d01);
            *(__half2*)(gd + (lr0 + 8) * 128 + lc) = __floats2half2_rn(d10, d11);
        }
    }

    red[tid] = (double)lsum;
    __syncthreads();
    #pragma unroll
    for (int s = 128; s > 0; s >>= 1) {
        if (tid < s) red[tid] += red[tid + s];
        __syncthreads();
    }
    if (tid == 0) atomicAdd(&g_distsum[z], red[0] * (double)w);
}

// ---------------------------------------------------------------------------
// Exponent pass, one CTA per tile. alphas are powers of two: with
// e = exp(-d/(4m)) the five kernels are e, e^2, e^4, e^8, e^16.
__global__ void exp_kernel() {
    __shared__ double red[256];
    int z, by, bx; float w;
    tile_decode(blockIdx.x, z, by, bx, w);

    double m = g_distsum[z] * (1.0 / ((double)BSZ * (double)BSZ));
    float c = (float)(-1.4426950408889634 / (4.0 * m));

    const uint4* src = (const uint4*)(g_dist + (size_t)blockIdx.x * TILE_ELEMS);
    float lsum = 0.f;
    #pragma unroll
    for (int it = 0; it < 8; it++) {
        uint4 v = src[it * 256 + threadIdx.x];
        uint32_t ww[4] = {v.x, v.y, v.z, v.w};
        #pragma unroll
        for (int u = 0; u < 4; u++) {
            float2 f = __half22float2(*(__half2*)&ww[u]);
            float d2[2] = {f.x, f.y};
            #pragma unroll
            for (int q = 0; q < 2; q++) {
                float t = d2[q] * c;
                float e;
                asm("ex2.approx.ftz.f32 %0, %1;" : "=f"(e) : "f"(t));
                float e2 = e * e, e4 = e2 * e2, e8 = e4 * e4, e16 = e8 * e8;
                lsum += (e + e2) + (e4 + e8) + e16;
            }
        }
    }

    red[threadIdx.x] = (double)lsum;
    __syncthreads();
    #pragma unroll
    for (int s = 128; s > 0; s >>= 1) {
        if (threadIdx.x < s) red[threadIdx.x] += red[threadIdx.x + s];
        __syncthreads();
    }
    if (threadIdx.x == 0) atomicAdd(&g_expsum[z], red[0] * (double)w);
}

// ---------------------------------------------------------------------------
__global__ void final_kernel(float* out) {
    double total = g_expsum[0] + g_expsum[1] - 2.0 * g_expsum[2];
    double v = total / ((double)BSZ * ((double)BSZ - 1.0));
    float loss = sqrtf((float)v);
    out[0] = isnan(loss) ? 0.f : loss;
}

// ---------------------------------------------------------------------------
extern "C" void kernel_launch(void* const* d_in, const int* in_sizes, int n_in,
                              void* d_out, int out_size) {
    const float* xs = (const float*)d_in[0];
    const float* xt = (const float*)d_in[1];
    float* out = (float*)d_out;

    static int configured = 0;
    if (!configured) {
        cudaFuncSetAttribute(dist_tc_kernel,
                             cudaFuncAttributeMaxDynamicSharedMemorySize, SM_BYTES);
        configured = 1;
    }

    zero_kernel<<<1, 32>>>();
    norms_kernel<<<1024, 256>>>(xs, xt);
    dist_tc_kernel<<<TILES_ALL, 256, SM_BYTES>>>(xs, xt);
    exp_kernel<<<TILES_ALL, 256>>>();
    final_kernel<<<1, 1>>>(out);
}